// round 7
// baseline (speedup 1.0000x reference)
#include <cuda_runtime.h>

// QuantumFeatureExtractor — analytic collapse, 2-warp vectorized fp32 path.
//
// out[b,i] = cos(x[b,i] + theta[i]); 320 outputs. At the ~4us launch floor;
// this trims the last warp: 64 threads (2 full warps), each handles one
// float4 of x, and threads 0-15 handle a second float4 (elements 256-319).
// theta stays SCALAR-loaded: float4 on d_in[1] (80B tensor) trapped on
// alignment in R4/R5 — do not reintroduce.

#define BATCH 16
#define N_QUBITS 20
#define TOTAL (BATCH * N_QUBITS)   // 320
#define NVEC (TOTAL / 4)           // 80 float4s
#define NTHREADS 64                // 2 full warps

__device__ __forceinline__ float4 qfe_vec(float4 v, const float* __restrict__ theta, int t) {
    // float4 index t covers elements [4t, 4t+4); q0 = (4t)%20 is a multiple
    // of 4 in [0,16], so thetas are theta[q0..q0+3], no wraparound.
    int q0 = (t % (N_QUBITS / 4)) * 4;
    float4 r;
    r.x = __cosf(v.x + theta[q0 + 0]);
    r.y = __cosf(v.y + theta[q0 + 1]);
    r.z = __cosf(v.z + theta[q0 + 2]);
    r.w = __cosf(v.w + theta[q0 + 3]);
    return r;
}

__global__ __launch_bounds__(NTHREADS, 1)
void qfe_kernel(const float4* __restrict__ x4,
                const float* __restrict__ theta,
                float4* __restrict__ out4) {
    int t = threadIdx.x;                  // 0..63
    // Front-batch both loads before any MUFU work (MLP).
    float4 v0 = x4[t];
    float4 v1;
    int t2 = t + NTHREADS;                // 64..127; valid when < 80
    bool second = (t2 < NVEC);            // threads 0..15
    if (second) v1 = x4[t2];
    out4[t] = qfe_vec(v0, theta, t);
    if (second) out4[t2] = qfe_vec(v1, theta, t2);
}

extern "C" void kernel_launch(void* const* d_in, const int* in_sizes, int n_in,
                              void* d_out, int out_size) {
    const float4* x4   = (const float4*)d_in[0];  // [16,20] fp32, 320 elems
    const float* theta = (const float*)d_in[1];   // [20] fp32
    float4* out4 = (float4*)d_out;                // [16,20] fp32
    qfe_kernel<<<1, NTHREADS>>>(x4, theta, out4);
}

// round 8
// speedup vs baseline: 1.2993x; 1.2993x over previous
#include <cuda_runtime.h>

// QuantumFeatureExtractor — analytic collapse, vectorized fp32 path.
// FROZEN best configuration (R6): 80 threads / 3 warps, one float4 per thread.
//
// out[b,i] = cos(x[b,i] + theta[i]); 320 outputs. Launch-floor bound (~4us);
// all pipes ~0% in ncu. Lessons baked in:
//  - fp64 cos: +1us on the weak FP64 pipe (R1) — use MUFU __cosf.
//  - float4 load of theta (d_in[1], 80B tensor): alignment trap, kills the
//    run (R4/R5) — theta stays scalar-loaded.
//  - folding tail work into fewer warps lengthens the slowest warp's serial
//    path and regresses ~1us (R7) — keep one float4 per thread, 3 warps.

#define BATCH 16
#define N_QUBITS 20
#define TOTAL (BATCH * N_QUBITS)   // 320
#define NTHREADS (TOTAL / 4)       // 80

__global__ __launch_bounds__(NTHREADS, 1)
void qfe_kernel(const float4* __restrict__ x4,
                const float* __restrict__ theta,
                float4* __restrict__ out4) {
    int t = threadIdx.x;           // 0..79
    float4 v = x4[t];
    // element base = 4t; q0 = (4t) % 20 is a multiple of 4 in [0,16],
    // so the 4 thetas for this thread are theta[q0..q0+3], no wraparound.
    int q0 = (t % (N_QUBITS / 4)) * 4;   // (t % 5) * 4
    float4 r;
    r.x = __cosf(v.x + theta[q0 + 0]);
    r.y = __cosf(v.y + theta[q0 + 1]);
    r.z = __cosf(v.z + theta[q0 + 2]);
    r.w = __cosf(v.w + theta[q0 + 3]);
    out4[t] = r;
}

extern "C" void kernel_launch(void* const* d_in, const int* in_sizes, int n_in,
                              void* d_out, int out_size) {
    const float4* x4   = (const float4*)d_in[0];  // [16,20] fp32, 320 elems
    const float* theta = (const float*)d_in[1];   // [20] fp32
    float4* out4 = (float4*)d_out;                // [16,20] fp32
    qfe_kernel<<<1, NTHREADS>>>(x4, theta, out4);
}